// round 15
// baseline (speedup 1.0000x reference)
#include <cuda_runtime.h>
#include <cstdint>

// ---------------- problem constants ----------------
#define B_        2
#define S_        2048
#define HID_      2048
#define HV_       32
#define HK_       16
#define DK_       128
#define DV_       128
#define KEY_DIM_  2048
#define VAL_DIM_  4096
#define CONV_DIM_ 8192
#define KS_       4
#define EPS_      1e-6f
#define BS_       (B_ * S_)          // 4096 rows

typedef unsigned long long u64;

// ---------------- scratch (static device globals; no allocations) ----------------
__device__ float g_qkv [(size_t)BS_ * CONV_DIM_];   // qkv projection
__device__ float g_zbuf[(size_t)BS_ * VAL_DIM_];    // z projection
__device__ float g_abuf[BS_ * HV_];                 // a projection
__device__ float g_bbuf[BS_ * HV_];                 // b projection
__device__ float g_qn  [(size_t)BS_ * HK_ * DK_];   // normalized q (HK heads)
__device__ float g_kn  [(size_t)BS_ * HK_ * DK_];   // normalized k
__device__ float g_vb  [(size_t)BS_ * HV_ * DV_];   // v after conv+silu
__device__ float g_g   [BS_ * HV_];                 // log-decay
__device__ float g_be  [BS_ * HV_];                 // beta
__device__ float g_or  [(size_t)BS_ * HV_ * DV_];   // raw scan output
__device__ float g_og  [(size_t)BS_ * VAL_DIM_];    // gated+normed output

// ---------------- f32x2 helpers ----------------
__device__ __forceinline__ u64 pk2(float lo, float hi) {
    u64 r; unsigned a = __float_as_uint(lo), b = __float_as_uint(hi);
    asm("mov.b64 %0, {%1, %2};" : "=l"(r) : "r"(a), "r"(b));
    return r;
}
__device__ __forceinline__ void up2(u64 v, float& lo, float& hi) {
    unsigned a, b;
    asm("mov.b64 {%0, %1}, %2;" : "=r"(a), "=r"(b) : "l"(v));
    lo = __uint_as_float(a); hi = __uint_as_float(b);
}
__device__ __forceinline__ u64 fma2(u64 a, u64 b, u64 c) {
    u64 d;
    asm("fma.rn.f32x2 %0, %1, %2, %3;" : "=l"(d) : "l"(a), "l"(b), "l"(c));
    return d;
}
__device__ __forceinline__ u64 mul2(u64 a, u64 b) {
    u64 d;
    asm("mul.rn.f32x2 %0, %1, %2;" : "=l"(d) : "l"(a), "l"(b));
    return d;
}

// ---------------- fp32 GEMM:  C[M,N] = A[M,K] @ W[N,K]^T ----------------
// 128x128 block tile, BK=16, 256 threads, 8x8 per-thread microtile as f32x2 pairs.
// Requires: M % 128 == 0, K % 16 == 0. N arbitrary (guarded).
__global__ void __launch_bounds__(256, 2)
gemm_tn(const float* __restrict__ A, const float* __restrict__ W,
        float* __restrict__ C, int M, int N, int K)
{
    __shared__ float As[16][132];
    __shared__ float Ws[16][132];

    const int tid = threadIdx.x;
    const int bm  = blockIdx.y * 128;
    const int bn  = blockIdx.x * 128;
    const int tm  = (tid >> 4) << 3;   // 0..120
    const int tn  = (tid & 15) << 3;   // 0..120

    u64 acc[8][4];
#pragma unroll
    for (int i = 0; i < 8; i++)
#pragma unroll
        for (int j = 0; j < 4; j++) acc[i][j] = 0ull;

    for (int k0 = 0; k0 < K; k0 += 16) {
        // load tiles (each thread: 2 float4 of A, 2 float4 of W), stored k-major
#pragma unroll
        for (int i = 0; i < 2; i++) {
            int f  = tid + i * 256;       // 0..511
            int r  = f >> 2;              // row within tile (0..127)
            int kc = (f & 3) << 2;        // k sub-chunk (0,4,8,12)
            float4 av = *(const float4*)(A + (size_t)(bm + r) * K + k0 + kc);
            As[kc + 0][r] = av.x; As[kc + 1][r] = av.y;
            As[kc + 2][r] = av.z; As[kc + 3][r] = av.w;
            float4 wv = make_float4(0.f, 0.f, 0.f, 0.f);
            if (bn + r < N)
                wv = *(const float4*)(W + (size_t)(bn + r) * K + k0 + kc);
            Ws[kc + 0][r] = wv.x; Ws[kc + 1][r] = wv.y;
            Ws[kc + 2][r] = wv.z; Ws[kc + 3][r] = wv.w;
        }
        __syncthreads();

#pragma unroll
        for (int kk = 0; kk < 16; kk++) {
            float4 a0 = *(const float4*)&As[kk][tm];
            float4 a1 = *(const float4*)&As[kk][tm + 4];
            ulonglong2 b01 = *(const ulonglong2*)&Ws[kk][tn];
            ulonglong2 b23 = *(const ulonglong2*)&Ws[kk][tn + 4];
            float am[8] = {a0.x, a0.y, a0.z, a0.w, a1.x, a1.y, a1.z, a1.w};
#pragma unroll
            for (int i = 0; i < 8; i++) {
                u64 a2 = pk2(am[i], am[i]);
                acc[i][0] = fma2(a2, b01.x, acc[i][0]);
                acc[i][1] = fma2(a2, b01.y, acc[i][1]);
                acc[i][2] = fma2(a2, b23.x, acc[i][2]);
                acc[i][3] = fma2(a2, b23.y, acc[i][3]);
            }
        }
        __syncthreads();
    }

#pragma unroll
    for (int i = 0; i < 8; i++) {
        float* crow = C + (size_t)(bm + tm + i) * N + bn + tn;
#pragma unroll
        for (int j = 0; j < 4; j++) {
            float lo, hi; up2(acc[i][j], lo, hi);
            int n = bn + tn + 2 * j;
            if (n     < N) crow[2 * j]     = lo;
            if (n + 1 < N) crow[2 * j + 1] = hi;
        }
    }
}

// ---------------- causal depthwise conv (KS=4) + SiLU + head split + l2norm ----------------
// grid = (64 channel-groups of 128, BS_), block = 128 threads (one channel each).
// groups [0,16): q heads -> l2norm * DK^-0.5 ; [16,32): k heads -> l2norm ; [32,64): v
__global__ void conv_prep(const float* __restrict__ qkv, const float* __restrict__ convw)
{
    const int t   = threadIdx.x;      // 0..127
    const int grp = blockIdx.x;       // 0..63
    const int bs  = blockIdx.y;       // 0..4095 (= b*S + s)
    const int s   = bs & (S_ - 1);
    const int c   = grp * 128 + t;

    float4 w = ((const float4*)convw)[c];
    float acc = 0.f;
#pragma unroll
    for (int kk = 0; kk < 4; kk++) {
        int sp = s - 3 + kk;
        float x = 0.f;
        if (sp >= 0) x = qkv[(size_t)(bs - 3 + kk) * CONV_DIM_ + c];
        float wk = (kk == 0) ? w.x : (kk == 1) ? w.y : (kk == 2) ? w.z : w.w;
        acc += x * wk;
    }
    float m = acc / (1.f + expf(-acc));    // SiLU

    if (grp < 32) {
        // l2 norm over this head's 128 channels
        float ss = m * m;
#pragma unroll
        for (int o = 16; o; o >>= 1) ss += __shfl_xor_sync(0xffffffffu, ss, o);
        __shared__ float rb[4];
        if ((t & 31) == 0) rb[t >> 5] = ss;
        __syncthreads();
        float nrm = fmaxf(sqrtf(rb[0] + rb[1] + rb[2] + rb[3]), EPS_);
        if (grp < 16)
            g_qn[((size_t)bs * HK_ + grp) * DK_ + t]        = m / nrm * 0.08838834764831845f; // DK^-0.5
        else
            g_kn[((size_t)bs * HK_ + (grp - 16)) * DK_ + t] = m / nrm;
    } else {
        g_vb[((size_t)bs * HV_ + (grp - 32)) * DV_ + t] = m;
    }
}

// ---------------- gates: g = -exp(A_log)*softplus(a+dt_bias), beta = sigmoid(b) ----------------
__global__ void gbeta_kernel(const float* __restrict__ A_log, const float* __restrict__ dt_bias)
{
    int i = blockIdx.x * blockDim.x + threadIdx.x;
    if (i >= BS_ * HV_) return;
    int h  = i & (HV_ - 1);
    float a = g_abuf[i] + dt_bias[h];
    float sp = (a > 20.f) ? a : log1pf(expf(a));
    g_g[i]  = -expf(A_log[h]) * sp;
    float b = g_bbuf[i];
    g_be[i] = 1.f / (1.f + expf(-b));
}

// ---------------- delta-rule scan: one CTA per (b,h), state in f32x2 registers ----------------
// 256 threads: thread t owns v-column (t&127) and k-half (t>>7) -> 64 state elems = 32 u64 regs.
__global__ void __launch_bounds__(256, 1)
scan_kernel()
{
    const int bh = blockIdx.x;        // b*HV + h
    const int b  = bh >> 5;
    const int h  = bh & 31;
    const int hk = h >> 1;            // repeat-interleave(2)
    const int t  = threadIdx.x;
    const int vc = t & 127;
    const int kh = t >> 7;

    __shared__ float ks[128], qs[128], vs[128];
    __shared__ float red1[256], red2[256];
    __shared__ float gb[2];

    u64 st[32];
#pragma unroll
    for (int i = 0; i < 32; i++) st[i] = 0ull;

    const float* kbase = g_kn + ((size_t)b * S_ * HK_ + hk) * DK_;
    const float* qbase = g_qn + ((size_t)b * S_ * HK_ + hk) * DK_;
    const float* vbase = g_vb + ((size_t)b * S_ * HV_ + h) * DV_;
    const float* gbase = g_g  + (size_t)b * S_ * HV_ + h;
    const float* bbase = g_be + (size_t)b * S_ * HV_ + h;
    float*       obase = g_or + ((size_t)b * S_ * HV_ + h) * DV_;

    // prefetch step 0
    float kr = 0.f, qr = 0.f, vr = 0.f, gr = 0.f, br = 0.f;
    if (t < 128) { kr = kbase[t]; qr = qbase[t]; }
    else         { vr = vbase[t - 128]; }
    if (t == 0)  { gr = gbase[0]; br = bbase[0]; }

    for (int s = 0; s < S_; s++) {
        __syncthreads();                       // prior step's smem fully consumed
        if (t < 128) { ks[t] = kr; qs[t] = qr; }
        else         { vs[t - 128] = vr; }
        if (t == 0)  { gb[0] = gr; gb[1] = br; }
        __syncthreads();

        if (s + 1 < S_) {                      // prefetch next step (hidden behind compute)
            size_t so = (size_t)(s + 1);
            if (t < 128) { kr = kbase[so * (HK_ * DK_) + t]; qr = qbase[so * (HK_ * DK_) + t]; }
            else         { vr = vbase[so * (HV_ * DV_) + (t - 128)]; }
            if (t == 0)  { gr = gbase[so * HV_]; br = bbase[so * HV_]; }
        }

        float eg = expf(gb[0]);
        float bt = gb[1];
        u64 eg2 = pk2(eg, eg);

        const ulonglong2* kp = (const ulonglong2*)&ks[kh * 64];
        const ulonglong2* qp = (const ulonglong2*)&qs[kh * 64];

        // phase 1: decay + kv = k . state
        u64 pkv = 0ull;
#pragma unroll
        for (int i = 0; i < 16; i++) {
            ulonglong2 kk = kp[i];
            st[2 * i]     = mul2(st[2 * i],     eg2);
            st[2 * i + 1] = mul2(st[2 * i + 1], eg2);
            pkv = fma2(kk.x, st[2 * i],     pkv);
            pkv = fma2(kk.y, st[2 * i + 1], pkv);
        }
        float plo, phi; up2(pkv, plo, phi);
        red1[t] = plo + phi;
        __syncthreads();

        float kv    = red1[vc] + red1[vc + 128];
        float delta = (vs[vc] - kv) * bt;
        u64 d2 = pk2(delta, delta);

        // phase 2: rank-1 update + out = q . state
        u64 po = 0ull;
#pragma unroll
        for (int i = 0; i < 16; i++) {
            ulonglong2 kk = kp[i];
            ulonglong2 qq = qp[i];
            st[2 * i]     = fma2(kk.x, d2, st[2 * i]);
            st[2 * i + 1] = fma2(kk.y, d2, st[2 * i + 1]);
            po = fma2(qq.x, st[2 * i],     po);
            po = fma2(qq.y, st[2 * i + 1], po);
        }
        up2(po, plo, phi);
        red2[t] = plo + phi;
        __syncthreads();

        if (kh == 0)
            obase[(size_t)s * (HV_ * DV_) + vc] = red2[vc] + red2[vc + 128];
    }
}

// ---------------- per-head RMSNorm * norm_w * SiLU(z) ----------------
// grid = BS_*HV_ blocks, 128 threads (one DV element each)
__global__ void normgate(const float* __restrict__ normw)
{
    const int idx = blockIdx.x;              // bs*HV + h
    const int t   = threadIdx.x;
    float o = g_or[(size_t)idx * DV_ + t];
    float ss = o * o;
#pragma unroll
    for (int of = 16; of; of >>= 1) ss += __shfl_xor_sync(0xffffffffu, ss, of);
    __shared__ float rb[4];
    if ((t & 31) == 0) rb[t >> 5] = ss;
    __syncthreads();
    float var = (rb[0] + rb[1] + rb[2] + rb[3]) * (1.f / 128.f);
    float r = rsqrtf(var + EPS_);

    int    h  = idx & (HV_ - 1);
    size_t bs = (size_t)(idx >> 5);
    float  z  = g_zbuf[bs * VAL_DIM_ + h * DV_ + t];
    float  sz = z / (1.f + expf(-z));
    g_og[bs * VAL_DIM_ + h * DV_ + t] = o * r * normw[t] * sz;
}

// ---------------- launch ----------------
extern "C" void kernel_launch(void* const* d_in, const int* in_sizes, int n_in,
                              void* d_out, int out_size)
{
    const float* hidden  = (const float*)d_in[0];
    const float* W_qkv   = (const float*)d_in[1];
    const float* W_z     = (const float*)d_in[2];
    const float* W_a     = (const float*)d_in[3];
    const float* W_b     = (const float*)d_in[4];
    const float* conv_w  = (const float*)d_in[5];
    const float* A_log   = (const float*)d_in[6];
    const float* dt_bias = (const float*)d_in[7];
    const float* norm_w  = (const float*)d_in[8];
    const float* W_out   = (const float*)d_in[9];
    float*       out     = (float*)d_out;

    float *qkv, *zb, *ab, *bb, *og;
    cudaGetSymbolAddress((void**)&qkv, g_qkv);
    cudaGetSymbolAddress((void**)&zb,  g_zbuf);
    cudaGetSymbolAddress((void**)&ab,  g_abuf);
    cudaGetSymbolAddress((void**)&bb,  g_bbuf);
    cudaGetSymbolAddress((void**)&og,  g_og);

    // projections
    gemm_tn<<<dim3(CONV_DIM_ / 128, BS_ / 128), 256>>>(hidden, W_qkv, qkv, BS_, CONV_DIM_, HID_);
    gemm_tn<<<dim3(VAL_DIM_  / 128, BS_ / 128), 256>>>(hidden, W_z,   zb,  BS_, VAL_DIM_,  HID_);
    gemm_tn<<<dim3(1,               BS_ / 128), 256>>>(hidden, W_a,   ab,  BS_, HV_,       HID_);
    gemm_tn<<<dim3(1,               BS_ / 128), 256>>>(hidden, W_b,   bb,  BS_, HV_,       HID_);

    // conv + silu + head split + l2norm
    conv_prep<<<dim3(64, BS_), 128>>>(qkv, conv_w);

    // gates
    gbeta_kernel<<<(BS_ * HV_ + 255) / 256, 256>>>(A_log, dt_bias);

    // delta-rule recurrence
    scan_kernel<<<B_ * HV_, 256>>>();

    // rmsnorm + z gate
    normgate<<<BS_ * HV_, 128>>>(norm_w);

    // output projection
    gemm_tn<<<dim3(HID_ / 128, BS_ / 128), 256>>>(og, W_out, out, BS_, HID_, VAL_DIM_);
}

// round 17
// speedup vs baseline: 1.9153x; 1.9153x over previous
#include <cuda_runtime.h>
#include <cuda_bf16.h>
#include <cstdint>

// ---------------- problem constants ----------------
#define B_        2
#define S_        2048
#define HID_      2048
#define HV_       32
#define HK_       16
#define DK_       128
#define DV_       128
#define KEY_DIM_  2048
#define VAL_DIM_  4096
#define CONV_DIM_ 8192
#define KS_       4
#define EPS_      1e-6f
#define BS_       (B_ * S_)          // 4096 rows

typedef unsigned long long u64;

// ---------------- scratch (static device globals; no allocations) ----------------
__device__ float g_qkv [(size_t)BS_ * CONV_DIM_];
__device__ float g_zbuf[(size_t)BS_ * VAL_DIM_];
__device__ float g_qn  [(size_t)BS_ * HK_ * DK_];
__device__ float g_kn  [(size_t)BS_ * HK_ * DK_];
__device__ float g_vb  [(size_t)BS_ * HV_ * DV_];
__device__ float g_g   [BS_ * HV_];
__device__ float g_be  [BS_ * HV_];
__device__ float g_or  [(size_t)BS_ * HV_ * DV_];
__device__ float g_og  [(size_t)BS_ * VAL_DIM_];
__device__ float g_abp [(size_t)32 * BS_ * 64];     // a/b split-K partials

// ---------------- f32x2 helpers (scan) ----------------
__device__ __forceinline__ u64 pk2(float lo, float hi) {
    u64 r; unsigned a = __float_as_uint(lo), b = __float_as_uint(hi);
    asm("mov.b64 %0, {%1, %2};" : "=l"(r) : "r"(a), "r"(b));
    return r;
}
__device__ __forceinline__ void up2(u64 v, float& lo, float& hi) {
    unsigned a, b;
    asm("mov.b64 {%0, %1}, %2;" : "=r"(a), "=r"(b) : "l"(v));
    lo = __uint_as_float(a); hi = __uint_as_float(b);
}
__device__ __forceinline__ u64 fma2(u64 a, u64 b, u64 c) {
    u64 d; asm("fma.rn.f32x2 %0, %1, %2, %3;" : "=l"(d) : "l"(a), "l"(b), "l"(c)); return d;
}
__device__ __forceinline__ u64 mul2(u64 a, u64 b) {
    u64 d; asm("mul.rn.f32x2 %0, %1, %2;" : "=l"(d) : "l"(a), "l"(b)); return d;
}

// ---------------- tensor-core helpers ----------------
__device__ __forceinline__ uint32_t smem_u32(const void* p) {
    uint32_t a;
    asm("{ .reg .u64 t; cvta.to.shared.u64 t, %1; cvt.u32.u64 %0, t; }" : "=r"(a) : "l"(p));
    return a;
}
__device__ __forceinline__ void ldsm_x4(uint32_t* r, uint32_t addr) {
    asm volatile("ldmatrix.sync.aligned.m8n8.x4.shared.b16 {%0,%1,%2,%3}, [%4];"
                 : "=r"(r[0]), "=r"(r[1]), "=r"(r[2]), "=r"(r[3]) : "r"(addr));
}
__device__ __forceinline__ void mma_bf16(float* d, const uint32_t* a, const uint32_t* b) {
    asm volatile("mma.sync.aligned.m16n8k16.row.col.f32.bf16.bf16.f32 "
                 "{%0,%1,%2,%3}, {%4,%5,%6,%7}, {%8,%9}, {%0,%1,%2,%3};"
                 : "+f"(d[0]), "+f"(d[1]), "+f"(d[2]), "+f"(d[3])
                 : "r"(a[0]), "r"(a[1]), "r"(a[2]), "r"(a[3]), "r"(b[0]), "r"(b[1]));
}
__device__ __forceinline__ uint32_t pkbf(__nv_bfloat16 a, __nv_bfloat16 b) {
    __nv_bfloat162 t; t.x = a; t.y = b; return *(uint32_t*)&t;
}
// split f32x4 into bf16 hi plane + bf16 residual plane (same smem layout, lstride apart)
__device__ __forceinline__ void st_split(__nv_bfloat16* hp, int lstride, float4 v) {
    __nv_bfloat16 hx = __float2bfloat16_rn(v.x), hy = __float2bfloat16_rn(v.y),
                  hz = __float2bfloat16_rn(v.z), hw = __float2bfloat16_rn(v.w);
    __nv_bfloat16 lx = __float2bfloat16_rn(v.x - __bfloat162float(hx)),
                  ly = __float2bfloat16_rn(v.y - __bfloat162float(hy)),
                  lz = __float2bfloat16_rn(v.z - __bfloat162float(hz)),
                  lw = __float2bfloat16_rn(v.w - __bfloat162float(hw));
    *(uint2*)hp             = make_uint2(pkbf(hx, hy), pkbf(hz, hw));
    *(uint2*)(hp + lstride) = make_uint2(pkbf(lx, ly), pkbf(lz, lw));
}

// =============== bf16 3-pass tensor GEMM: C[M,N] = A[M,K] @ W[N,K]^T ===============
// 128x128 block, BK=32, 256 thr (8 warps, 4x2), double-buffered hi/lo bf16 smem.
// M,N multiples of 128; K multiple of 32.
// SAW=40: row stride 80B -> 16B-aligned ldmatrix rows, conflict-free 8-row pattern.
#define SAW   40
#define TILEE (128 * SAW)   // elems per (buf,plane) tile

__global__ void __launch_bounds__(256, 1)
gemm_bf3(const float* __restrict__ A, const float* __restrict__ W,
         float* __restrict__ C, int N, int K)
{
    extern __shared__ __nv_bfloat16 sm[];
    __nv_bfloat16* sA = sm;               // [buf2][plane2][TILEE]
    __nv_bfloat16* sW = sm + 4 * TILEE;

    const int tid = threadIdx.x, lane = tid & 31, wid = tid >> 5;
    const int wm = wid & 3, wn = wid >> 2;
    const int bm = blockIdx.y * 128, bn = blockIdx.x * 128;

    const uint32_t sbA = smem_u32(sA);
    const uint32_t sbW = smem_u32(sW);
    // A fragment addressing (16x16 block): lanes 0-15 rows 0-15 (k 0-7),
    // lanes 16-31 rows 0-15 (k 8-15)
    const int arow = wm * 32 + (lane & 15);
    const int acol = (lane >> 4) * 8;
    // B (W) fragment addressing, NON-trans: lanes 0-7: n0-7/k0; 8-15: n0-7/k8;
    // 16-23: n8-15/k0; 24-31: n8-15/k8
    const int brow = wn * 64 + ((lane >> 4) & 1) * 8 + (lane & 7);
    const int bcol = ((lane >> 3) & 1) * 8;

    float acc[2][8][4];
#pragma unroll
    for (int i = 0; i < 2; i++)
#pragma unroll
        for (int j = 0; j < 8; j++)
#pragma unroll
            for (int q = 0; q < 4; q++) acc[i][j][q] = 0.f;

    float4 ra[4], rw[4];
    auto ldg = [&](int blk) {
        int k0 = blk * 32;
#pragma unroll
        for (int i = 0; i < 4; i++) {
            int f = tid + i * 256, r = f >> 3, kc = (f & 7) << 2;
            ra[i] = *(const float4*)(A + (size_t)(bm + r) * K + k0 + kc);
            rw[i] = *(const float4*)(W + (size_t)(bn + r) * K + k0 + kc);
        }
    };
    auto sts = [&](int buf) {
#pragma unroll
        for (int i = 0; i < 4; i++) {
            int f = tid + i * 256, r = f >> 3, kc = (f & 7) << 2;
            st_split(sA + (buf * 2) * TILEE + r * SAW + kc, TILEE, ra[i]);
            st_split(sW + (buf * 2) * TILEE + r * SAW + kc, TILEE, rw[i]);
        }
    };

    const int nkb = K >> 5;
    ldg(0); sts(0);
    __syncthreads();

    for (int blk = 0; blk < nkb; blk++) {
        int p = blk & 1;
        if (blk + 1 < nkb) ldg(blk + 1);
#pragma unroll
        for (int pass = 0; pass < 3; pass++) {
            // D = Ah*Wh + Ah*Wl + Al*Wh
            const uint32_t aoff = sbA + (uint32_t)((p * 2 + (pass == 2)) * TILEE) * 2;
            const uint32_t woff = sbW + (uint32_t)((p * 2 + (pass == 1)) * TILEE) * 2;
#pragma unroll
            for (int kk = 0; kk < 2; kk++) {
                uint32_t afr[2][4], bfr[4][4];
#pragma unroll
                for (int mi = 0; mi < 2; mi++)
                    ldsm_x4(afr[mi], aoff + (uint32_t)((arow + mi * 16) * SAW + kk * 16 + acol) * 2);
#pragma unroll
                for (int nj = 0; nj < 4; nj++)
                    ldsm_x4(bfr[nj], woff + (uint32_t)((brow + nj * 16) * SAW + kk * 16 + bcol) * 2);
#pragma unroll
                for (int mi = 0; mi < 2; mi++)
#pragma unroll
                    for (int ni = 0; ni < 8; ni++)
                        mma_bf16(acc[mi][ni], afr[mi], &bfr[ni >> 1][(ni & 1) * 2]);
            }
        }
        __syncthreads();
        if (blk + 1 < nkb) { sts((blk + 1) & 1); __syncthreads(); }
    }

#pragma unroll
    for (int mi = 0; mi < 2; mi++) {
        int r0 = bm + wm * 32 + mi * 16 + (lane >> 2);
#pragma unroll
        for (int ni = 0; ni < 8; ni++) {
            int cc = bn + wn * 64 + ni * 8 + (lane & 3) * 2;
            *(float2*)(C + (size_t)r0 * N + cc)       = make_float2(acc[mi][ni][0], acc[mi][ni][1]);
            *(float2*)(C + (size_t)(r0 + 8) * N + cc) = make_float2(acc[mi][ni][2], acc[mi][ni][3]);
        }
    }
}

// =============== a/b projections: split-K partial + fused reduce ===============
__global__ void __launch_bounds__(256, 1)
ab_partial(const float* __restrict__ hidden, const float* __restrict__ W_a,
           const float* __restrict__ W_b)
{
    __shared__ float As[64][65];
    __shared__ float Ws[64][65];
    const int tid = threadIdx.x;
    const int m0 = blockIdx.x * 64;
    const int k0 = blockIdx.y * 64;

#pragma unroll
    for (int i = 0; i < 4; i++) {
        int f = tid + i * 256, r = f >> 4, c = (f & 15) << 2;
        float4 v = *(const float4*)(hidden + (size_t)(m0 + r) * HID_ + k0 + c);
        As[r][c] = v.x; As[r][c + 1] = v.y; As[r][c + 2] = v.z; As[r][c + 3] = v.w;
        const float* wrow = (r < 32) ? (W_a + (size_t)r * HID_) : (W_b + (size_t)(r - 32) * HID_);
        float4 w = *(const float4*)(wrow + k0 + c);
        Ws[r][c] = w.x; Ws[r][c + 1] = w.y; Ws[r][c + 2] = w.z; Ws[r][c + 3] = w.w;
    }
    __syncthreads();

    const int c = tid & 63, g = tid >> 6;
    float acc[16];
#pragma unroll
    for (int i = 0; i < 16; i++) acc[i] = 0.f;
    for (int kk = 0; kk < 64; kk++) {
        float w = Ws[c][kk];
#pragma unroll
        for (int i = 0; i < 16; i++) acc[i] += As[g * 16 + i][kk] * w;
    }
    float* dst = g_abp + ((size_t)blockIdx.y * BS_ + m0) * 64;
#pragma unroll
    for (int i = 0; i < 16; i++) dst[(size_t)(g * 16 + i) * 64 + c] = acc[i];
}

__global__ void ab_reduce(const float* __restrict__ A_log, const float* __restrict__ dt_bias)
{
    int i = blockIdx.x * 256 + threadIdx.x;          // < BS_*64
    int m = i >> 6, c = i & 63;
    float s = 0.f;
#pragma unroll
    for (int ky = 0; ky < 32; ky++) s += g_abp[((size_t)ky * BS_ + m) * 64 + c];
    if (c < 32) {
        float a  = s + dt_bias[c];
        float sp = (a > 20.f) ? a : log1pf(expf(a));
        g_g[m * 32 + c] = -expf(A_log[c]) * sp;
    } else {
        g_be[m * 32 + (c - 32)] = 1.f / (1.f + expf(-s));
    }
}

// ---------------- causal depthwise conv (KS=4) + SiLU + head split + l2norm ----------------
__global__ void conv_prep(const float* __restrict__ qkv, const float* __restrict__ convw)
{
    const int t   = threadIdx.x;      // 0..127
    const int grp = blockIdx.x;       // 0..63
    const int bs  = blockIdx.y;       // 0..4095
    const int s   = bs & (S_ - 1);
    const int c   = grp * 128 + t;

    float4 w = ((const float4*)convw)[c];
    float acc = 0.f;
#pragma unroll
    for (int kk = 0; kk < 4; kk++) {
        int sp = s - 3 + kk;
        float x = 0.f;
        if (sp >= 0) x = qkv[(size_t)(bs - 3 + kk) * CONV_DIM_ + c];
        float wk = (kk == 0) ? w.x : (kk == 1) ? w.y : (kk == 2) ? w.z : w.w;
        acc += x * wk;
    }
    float m = acc / (1.f + expf(-acc));    // SiLU

    if (grp < 32) {
        float ss = m * m;
#pragma unroll
        for (int o = 16; o; o >>= 1) ss += __shfl_xor_sync(0xffffffffu, ss, o);
        __shared__ float rb[4];
        if ((t & 31) == 0) rb[t >> 5] = ss;
        __syncthreads();
        float nrm = fmaxf(sqrtf(rb[0] + rb[1] + rb[2] + rb[3]), EPS_);
        if (grp < 16)
            g_qn[((size_t)bs * HK_ + grp) * DK_ + t]        = m / nrm * 0.08838834764831845f;
        else
            g_kn[((size_t)bs * HK_ + (grp - 16)) * DK_ + t] = m / nrm;
    } else {
        g_vb[((size_t)bs * HV_ + (grp - 32)) * DV_ + t] = m;
    }
}

// ---------------- delta-rule scan ----------------
__global__ void __launch_bounds__(256, 1)
scan_kernel()
{
    const int bh = blockIdx.x;
    const int b  = bh >> 5;
    const int h  = bh & 31;
    const int hk = h >> 1;
    const int t  = threadIdx.x;
    const int vc = t & 127;
    const int kh = t >> 7;

    __shared__ float ks[128], qs[128], vs[128];
    __shared__ float red1[256], red2[256];
    __shared__ float gb[2];

    u64 st[32];
#pragma unroll
    for (int i = 0; i < 32; i++) st[i] = 0ull;

    const float* kbase = g_kn + ((size_t)b * S_ * HK_ + hk) * DK_;
    const float* qbase = g_qn + ((size_t)b * S_ * HK_ + hk) * DK_;
    const float* vbase = g_vb + ((size_t)b * S_ * HV_ + h) * DV_;
    const float* gbase = g_g  + (size_t)b * S_ * HV_ + h;
    const float* bbase = g_be + (size_t)b * S_ * HV_ + h;
    float*       obase = g_or + ((size_t)b * S_ * HV_ + h) * DV_;

    float kr = 0.f, qr = 0.f, vr = 0.f, gr = 0.f, br = 0.f;
    if (t < 128) { kr = kbase[t]; qr = qbase[t]; }
    else         { vr = vbase[t - 128]; }
    if (t == 0)  { gr = gbase[0]; br = bbase[0]; }

    for (int s = 0; s < S_; s++) {
        __syncthreads();
        if (t < 128) { ks[t] = kr; qs[t] = qr; }
        else         { vs[t - 128] = vr; }
        if (t == 0)  { gb[0] = gr; gb[1] = br; }
        __syncthreads();

        if (s + 1 < S_) {
            size_t so = (size_t)(s + 1);
            if (t < 128) { kr = kbase[so * (HK_ * DK_) + t]; qr = qbase[so * (HK_ * DK_) + t]; }
            else         { vr = vbase[so * (HV_ * DV_) + (t - 128)]; }
            if (t == 0)  { gr = gbase[so * HV_]; br = bbase[so * HV_]; }
        }

        float eg = expf(gb[0]);
        float bt = gb[1];
        u64 eg2 = pk2(eg, eg);

        const ulonglong2* kp = (const ulonglong2*)&ks[kh * 64];
        const ulonglong2* qp = (const ulonglong2*)&qs[kh * 64];

        u64 pkv = 0ull;
#pragma unroll
        for (int i = 0; i < 16; i++) {
            ulonglong2 kk = kp[i];
            st[2 * i]     = mul2(st[2 * i],     eg2);
            st[2 * i + 1] = mul2(st[2 * i + 1], eg2);
            pkv = fma2(kk.x, st[2 * i],     pkv);
            pkv = fma2(kk.y, st[2 * i + 1], pkv);
        }
        float plo, phi; up2(pkv, plo, phi);
        red1[t] = plo + phi;
        __syncthreads();

        float kv    = red1[vc] + red1[vc + 128];
        float delta = (vs[vc] - kv) * bt;
        u64 d2 = pk2(delta, delta);

        u64 po = 0ull;
#pragma unroll
        for (int i = 0; i < 16; i++) {
            ulonglong2 kk = kp[i];
            ulonglong2 qq = qp[i];
            st[2 * i]     = fma2(kk.x, d2, st[2 * i]);
            st[2 * i + 1] = fma2(kk.y, d2, st[2 * i + 1]);
            po = fma2(qq.x, st[2 * i],     po);
            po = fma2(qq.y, st[2 * i + 1], po);
        }
        up2(po, plo, phi);
        red2[t] = plo + phi;
        __syncthreads();

        if (kh == 0)
            obase[(size_t)s * (HV_ * DV_) + vc] = red2[vc] + red2[vc + 128];
    }
}

// ---------------- per-head RMSNorm * norm_w * SiLU(z) ----------------
__global__ void normgate(const float* __restrict__ normw)
{
    const int idx = blockIdx.x;
    const int t   = threadIdx.x;
    float o = g_or[(size_t)idx * DV_ + t];
    float ss = o * o;
#pragma unroll
    for (int of = 16; of; of >>= 1) ss += __shfl_xor_sync(0xffffffffu, ss, of);
    __shared__ float rb[4];
    if ((t & 31) == 0) rb[t >> 5] = ss;
    __syncthreads();
    float var = (rb[0] + rb[1] + rb[2] + rb[3]) * (1.f / 128.f);
    float r = rsqrtf(var + EPS_);

    int    h  = idx & (HV_ - 1);
    size_t bs = (size_t)(idx >> 5);
    float  z  = g_zbuf[bs * VAL_DIM_ + h * DV_ + t];
    float  sz = z / (1.f + expf(-z));
    g_og[bs * VAL_DIM_ + h * DV_ + t] = o * r * normw[t] * sz;
}

// ---------------- launch ----------------
extern "C" void kernel_launch(void* const* d_in, const int* in_sizes, int n_in,
                              void* d_out, int out_size)
{
    const float* hidden  = (const float*)d_in[0];
    const float* W_qkv   = (const float*)d_in[1];
    const float* W_z     = (const float*)d_in[2];
    const float* W_a     = (const float*)d_in[3];
    const float* W_b     = (const float*)d_in[4];
    const float* conv_w  = (const float*)d_in[5];
    const float* A_log   = (const float*)d_in[6];
    const float* dt_bias = (const float*)d_in[7];
    const float* norm_w  = (const float*)d_in[8];
    const float* W_out   = (const float*)d_in[9];
    float*       out     = (float*)d_out;

    float *qkv, *zb, *og;
    cudaGetSymbolAddress((void**)&qkv, g_qkv);
    cudaGetSymbolAddress((void**)&zb,  g_zbuf);
    cudaGetSymbolAddress((void**)&og,  g_og);

    const int GSM = 8 * TILEE * 2;   // 81920 B dynamic smem
    cudaFuncSetAttribute(gemm_bf3, cudaFuncAttributeMaxDynamicSharedMemorySize, GSM);

    // projections (tensor cores, bf16 3-pass split)
    gemm_bf3<<<dim3(CONV_DIM_ / 128, BS_ / 128), 256, GSM>>>(hidden, W_qkv, qkv, CONV_DIM_, HID_);
    gemm_bf3<<<dim3(VAL_DIM_  / 128, BS_ / 128), 256, GSM>>>(hidden, W_z,   zb,  VAL_DIM_,  HID_);

    // a/b projections + gates (split-K)
    ab_partial<<<dim3(BS_ / 64, 32), 256>>>(hidden, W_a, W_b);
    ab_reduce<<<(BS_ * 64) / 256, 256>>>(A_log, dt_bias);

    // conv + silu + head split + l2norm
    conv_prep<<<dim3(64, BS_), 128>>>(qkv, conv_w);

    // delta-rule recurrence
    scan_kernel<<<B_ * HV_, 256>>>();

    // rmsnorm + z gate
    normgate<<<BS_ * HV_, 128>>>(norm_w);

    // output projection
    gemm_bf3<<<dim3(HID_ / 128, BS_ / 128), 256, GSM>>>(og, W_out, out, HID_, VAL_DIM_);
}